// round 6
// baseline (speedup 1.0000x reference)
#include <cuda_runtime.h>

#define N_NODES 80000
#define N_EDGES 1280000
#define IN_CH 128
#define HID 64
#define OUT_CH 32

#define SCAN_BLK 512
#define N_SCAN_BLOCKS ((N_NODES + SCAN_BLK - 1) / SCAN_BLK)   // 157

__device__ __align__(256) float g_dinv[N_NODES];
__device__ __align__(256) int   g_cnt [N_NODES];
__device__ __align__(256) int   g_offs[N_NODES + 1];
__device__ __align__(256) int   g_cursor[N_NODES];
__device__ __align__(256) int   g_bsum[N_SCAN_BLOCKS];
__device__ __align__(256) int   g_csr [N_EDGES];
__device__ __align__(256) float g_h1s [(size_t)N_NODES * HID];     // dinv*(x@W1)
__device__ __align__(256) float g_out1[(size_t)N_NODES * HID];     // relu(b1 + ...)
__device__ __align__(256) float g_h2s [(size_t)N_NODES * OUT_CH];  // dinv*(out1@W2)

// ---------------- CSR build ----------------

__global__ void k_zero_cnt() {
    int i = blockIdx.x * blockDim.x + threadIdx.x;
    if (i < N_NODES) g_cnt[i] = 0;
}

__global__ void k_cnt(const int* __restrict__ dst) {
    int e = blockIdx.x * blockDim.x + threadIdx.x;
    if (e < N_EDGES) atomicAdd(&g_cnt[dst[e]], 1);
}

__global__ void k_dinv() {
    int i = blockIdx.x * blockDim.x + threadIdx.x;
    if (i < N_NODES) g_dinv[i] = rsqrtf((float)(g_cnt[i] + 1));  // + self loop
}

__global__ void __launch_bounds__(SCAN_BLK) k_scan1() {
    __shared__ int s[2 * SCAN_BLK];
    int t = threadIdx.x;
    int gi = blockIdx.x * SCAN_BLK + t;
    int v = (gi < N_NODES) ? g_cnt[gi] : 0;
    int* a = s; int* b = s + SCAN_BLK;
    a[t] = v;
    __syncthreads();
#pragma unroll
    for (int off = 1; off < SCAN_BLK; off <<= 1) {
        b[t] = a[t] + ((t >= off) ? a[t - off] : 0);
        int* tmp = a; a = b; b = tmp;
        __syncthreads();
    }
    if (gi < N_NODES) g_offs[gi] = a[t] - v;
    if (t == SCAN_BLK - 1) g_bsum[blockIdx.x] = a[t];
}

// parallel scan of 157 block sums (one 256-thread block)
__global__ void __launch_bounds__(256) k_scan2() {
    __shared__ int s[2 * 256];
    int t = threadIdx.x;
    int v = (t < N_SCAN_BLOCKS) ? g_bsum[t] : 0;
    int* a = s; int* b = s + 256;
    a[t] = v;
    __syncthreads();
#pragma unroll
    for (int off = 1; off < 256; off <<= 1) {
        b[t] = a[t] + ((t >= off) ? a[t - off] : 0);
        int* tmp = a; a = b; b = tmp;
        __syncthreads();
    }
    if (t < N_SCAN_BLOCKS) g_bsum[t] = a[t] - v;   // exclusive
    if (t == 0) g_offs[N_NODES] = N_EDGES;
}

__global__ void k_scan3() {
    int gi = blockIdx.x * blockDim.x + threadIdx.x;
    if (gi < N_NODES) {
        int o = g_offs[gi] + g_bsum[gi / SCAN_BLK];
        g_offs[gi] = o;
        g_cursor[gi] = o;
    }
}

__global__ void k_fill(const int* __restrict__ src, const int* __restrict__ dst) {
    int e = blockIdx.x * blockDim.x + threadIdx.x;
    if (e < N_EDGES) {
        int pos = atomicAdd(&g_cursor[dst[e]], 1);
        g_csr[pos] = src[e];
    }
}

// ---------------- GEMM1: h1s = dinv * (x @ W1) (128 -> 64) ----------------
// 128 threads/block, tile 128 nodes x 64 ch, thread = 4 nodes x 16 ch (R3 proven).

__global__ void __launch_bounds__(128) k_gemm1(const float* __restrict__ x,
                                               const float* __restrict__ W1) {
    __shared__ float sW[32 * 64];
    __shared__ float sX[128 * 33];
    const int tn = threadIdx.x & 3;
    const int tm = threadIdx.x >> 2;
    const int cg = tn << 4;
    const int nodeBase = blockIdx.x * 128;

    float acc[4][16];
#pragma unroll
    for (int j = 0; j < 4; j++)
#pragma unroll
        for (int c = 0; c < 16; c++) acc[j][c] = 0.0f;

    for (int kt = 0; kt < IN_CH; kt += 32) {
#pragma unroll
        for (int i = threadIdx.x; i < 512; i += 128)
            ((float4*)sW)[i] =
                ((const float4*)W1)[(size_t)(kt + (i >> 4)) * 16 + (i & 15)];
#pragma unroll
        for (int i = threadIdx.x; i < 1024; i += 128) {
            int n = i >> 3, f4 = i & 7;
            float4 v = ((const float4*)x)[(size_t)(nodeBase + n) * 32 + (kt >> 2) + f4];
            float* p = sX + n * 33 + (f4 << 2);
            p[0] = v.x; p[1] = v.y; p[2] = v.z; p[3] = v.w;
        }
        __syncthreads();
#pragma unroll 2
        for (int k = 0; k < 32; ++k) {
            const float4* w4 = (const float4*)(sW + k * 64 + cg);
            float4 w0 = w4[0], w1 = w4[1], w2 = w4[2], w3 = w4[3];
            float xv[4];
#pragma unroll
            for (int j = 0; j < 4; j++) xv[j] = sX[(tm * 4 + j) * 33 + k];
#pragma unroll
            for (int j = 0; j < 4; j++) {
                acc[j][0]  += xv[j] * w0.x;  acc[j][1]  += xv[j] * w0.y;
                acc[j][2]  += xv[j] * w0.z;  acc[j][3]  += xv[j] * w0.w;
                acc[j][4]  += xv[j] * w1.x;  acc[j][5]  += xv[j] * w1.y;
                acc[j][6]  += xv[j] * w1.z;  acc[j][7]  += xv[j] * w1.w;
                acc[j][8]  += xv[j] * w2.x;  acc[j][9]  += xv[j] * w2.y;
                acc[j][10] += xv[j] * w2.z;  acc[j][11] += xv[j] * w2.w;
                acc[j][12] += xv[j] * w3.x;  acc[j][13] += xv[j] * w3.y;
                acc[j][14] += xv[j] * w3.z;  acc[j][15] += xv[j] * w3.w;
            }
        }
        __syncthreads();
    }
#pragma unroll
    for (int j = 0; j < 4; j++) {
        int node = nodeBase + tm * 4 + j;
        float dj = g_dinv[node];
        float4* out = (float4*)(g_h1s + (size_t)node * HID + cg);
#pragma unroll
        for (int q = 0; q < 4; q++)
            out[q] = make_float4(dj * acc[j][4 * q], dj * acc[j][4 * q + 1],
                                 dj * acc[j][4 * q + 2], dj * acc[j][4 * q + 3]);
    }
}

// ---------------- agg1 (warp/node, lane = 2 ch, MLP-4 unroll) ----------------

__global__ void __launch_bounds__(256) k_agg1(const float* __restrict__ b1) {
    int node = blockIdx.x * 8 + (threadIdx.x >> 5);
    if (node >= N_NODES) return;
    int lane = threadIdx.x & 31;
    const float2* h = (const float2*)g_h1s;
    int beg = g_offs[node], end = g_offs[node + 1];
    float2 a0 = h[(size_t)node * 32 + lane];   // self
    float2 a1 = make_float2(0.f, 0.f), a2 = a1, a3 = a1;
    for (int c = beg; c < end; c += 32) {
        int m = min(32, end - c);
        int idx = (lane < m) ? g_csr[c + lane] : 0;
        int t = 0;
        for (; t + 4 <= m; t += 4) {
            int j0 = __shfl_sync(0xffffffffu, idx, t);
            int j1 = __shfl_sync(0xffffffffu, idx, t + 1);
            int j2 = __shfl_sync(0xffffffffu, idx, t + 2);
            int j3 = __shfl_sync(0xffffffffu, idx, t + 3);
            float2 v0 = h[(size_t)j0 * 32 + lane];
            float2 v1 = h[(size_t)j1 * 32 + lane];
            float2 v2 = h[(size_t)j2 * 32 + lane];
            float2 v3 = h[(size_t)j3 * 32 + lane];
            a0.x += v0.x; a0.y += v0.y;
            a1.x += v1.x; a1.y += v1.y;
            a2.x += v2.x; a2.y += v2.y;
            a3.x += v3.x; a3.y += v3.y;
        }
        for (; t < m; ++t) {
            int j = __shfl_sync(0xffffffffu, idx, t);
            float2 v = h[(size_t)j * 32 + lane];
            a0.x += v.x; a0.y += v.y;
        }
    }
    float di = g_dinv[node];
    float accx = (a0.x + a1.x) + (a2.x + a3.x);
    float accy = (a0.y + a1.y) + (a2.y + a3.y);
    float2 bv = ((const float2*)b1)[lane];
    ((float2*)g_out1)[(size_t)node * 32 + lane] =
        make_float2(fmaxf(bv.x + di * accx, 0.0f),
                    fmaxf(bv.y + di * accy, 0.0f));
}

// ---------------- GEMM2: h2s = dinv * (out1 @ W2) (64 -> 32) ----------------
// 128 threads/block, thread = 4 nodes x 8 ch (R3 proven).

__global__ void __launch_bounds__(128) k_gemm2(const float* __restrict__ W2) {
    __shared__ float sW[64 * 32];
    __shared__ float sX[128 * 65];
    const int tn = threadIdx.x & 3;
    const int tm = threadIdx.x >> 2;
    const int cg = tn << 3;
    const int nodeBase = blockIdx.x * 128;

#pragma unroll
    for (int i = threadIdx.x; i < 512; i += 128)
        ((float4*)sW)[i] = ((const float4*)W2)[i];
#pragma unroll
    for (int i = threadIdx.x; i < 2048; i += 128) {
        int n = i >> 4, f4 = i & 15;
        float4 v = ((const float4*)g_out1)[(size_t)(nodeBase + n) * 16 + f4];
        float* p = sX + n * 65 + (f4 << 2);
        p[0] = v.x; p[1] = v.y; p[2] = v.z; p[3] = v.w;
    }
    __syncthreads();

    float acc[4][8];
#pragma unroll
    for (int j = 0; j < 4; j++)
#pragma unroll
        for (int c = 0; c < 8; c++) acc[j][c] = 0.0f;

#pragma unroll 4
    for (int k = 0; k < HID; ++k) {
        const float4* w4 = (const float4*)(sW + k * 32 + cg);
        float4 w0 = w4[0], w1 = w4[1];
        float xv[4];
#pragma unroll
        for (int j = 0; j < 4; j++) xv[j] = sX[(tm * 4 + j) * 65 + k];
#pragma unroll
        for (int j = 0; j < 4; j++) {
            acc[j][0] += xv[j] * w0.x; acc[j][1] += xv[j] * w0.y;
            acc[j][2] += xv[j] * w0.z; acc[j][3] += xv[j] * w0.w;
            acc[j][4] += xv[j] * w1.x; acc[j][5] += xv[j] * w1.y;
            acc[j][6] += xv[j] * w1.z; acc[j][7] += xv[j] * w1.w;
        }
    }
#pragma unroll
    for (int j = 0; j < 4; j++) {
        int node = nodeBase + tm * 4 + j;
        float dj = g_dinv[node];
        float4* out = (float4*)(g_h2s + (size_t)node * OUT_CH + cg);
        out[0] = make_float4(dj * acc[j][0], dj * acc[j][1],
                             dj * acc[j][2], dj * acc[j][3]);
        out[1] = make_float4(dj * acc[j][4], dj * acc[j][5],
                             dj * acc[j][6], dj * acc[j][7]);
    }
}

// ---------------- agg2 (warp/node, lane = 1 ch, MLP-4 unroll) ----------------

__global__ void __launch_bounds__(256) k_agg2(const float* __restrict__ b2,
                                              float* __restrict__ out) {
    int node = blockIdx.x * 8 + (threadIdx.x >> 5);
    if (node >= N_NODES) return;
    int lane = threadIdx.x & 31;
    int beg = g_offs[node], end = g_offs[node + 1];
    float a0 = g_h2s[(size_t)node * 32 + lane];
    float a1 = 0.f, a2 = 0.f, a3 = 0.f;
    for (int c = beg; c < end; c += 32) {
        int m = min(32, end - c);
        int idx = (lane < m) ? g_csr[c + lane] : 0;
        int t = 0;
        for (; t + 4 <= m; t += 4) {
            int j0 = __shfl_sync(0xffffffffu, idx, t);
            int j1 = __shfl_sync(0xffffffffu, idx, t + 1);
            int j2 = __shfl_sync(0xffffffffu, idx, t + 2);
            int j3 = __shfl_sync(0xffffffffu, idx, t + 3);
            a0 += g_h2s[(size_t)j0 * 32 + lane];
            a1 += g_h2s[(size_t)j1 * 32 + lane];
            a2 += g_h2s[(size_t)j2 * 32 + lane];
            a3 += g_h2s[(size_t)j3 * 32 + lane];
        }
        for (; t < m; ++t) {
            int j = __shfl_sync(0xffffffffu, idx, t);
            a0 += g_h2s[(size_t)j * 32 + lane];
        }
    }
    float di = g_dinv[node];
    out[(size_t)node * 32 + lane] = b2[lane] + di * ((a0 + a1) + (a2 + a3));
}

// ---------------- launch (single stream, R4-proven order) ----------------

extern "C" void kernel_launch(void* const* d_in, const int* in_sizes, int n_in,
                              void* d_out, int out_size) {
    const float* x   = (const float*)d_in[0];
    const int*   ei  = (const int*)d_in[1];
    const float* W1  = (const float*)d_in[2];
    const float* b1  = (const float*)d_in[3];
    const float* W2  = (const float*)d_in[4];
    const float* b2  = (const float*)d_in[5];
    float*       out = (float*)d_out;

    const int* src = ei;
    const int* dst = ei + N_EDGES;

    k_zero_cnt<<<(N_NODES + 255) / 256, 256>>>();
    k_cnt     <<<(N_EDGES + 255) / 256, 256>>>(dst);
    k_dinv    <<<(N_NODES + 255) / 256, 256>>>();
    k_scan1   <<<N_SCAN_BLOCKS, SCAN_BLK>>>();
    k_scan2   <<<1, 256>>>();
    k_scan3   <<<(N_NODES + 255) / 256, 256>>>();
    k_fill    <<<(N_EDGES + 255) / 256, 256>>>(src, dst);

    k_gemm1   <<<N_NODES / 128, 128>>>(x, W1);
    k_agg1    <<<(N_NODES + 7) / 8, 256>>>(b1);
    k_gemm2   <<<N_NODES / 128, 128>>>(W2);
    k_agg2    <<<(N_NODES + 7) / 8, 256>>>(b2, out);
}

// round 7
// speedup vs baseline: 1.4793x; 1.4793x over previous
#include <cuda_runtime.h>

#define N_NODES 80000
#define N_EDGES 1280000
#define IN_CH 128
#define HID 64
#define OUT_CH 32

#define SCAN_BLK 512
#define N_SCAN_BLOCKS ((N_NODES + SCAN_BLK - 1) / SCAN_BLK)   // 157

__device__ __align__(256) float g_dinv[N_NODES];
__device__ __align__(256) int   g_cnt [N_NODES];
__device__ __align__(256) int   g_offs[N_NODES + 1];
__device__ __align__(256) int   g_cursor[N_NODES];
__device__ __align__(256) int   g_bsum[N_SCAN_BLOCKS];
__device__ __align__(256) int   g_csr [N_EDGES];
__device__ __align__(256) float g_h1s [(size_t)N_NODES * HID];     // dinv*(x@W1)
__device__ __align__(256) float g_out1[(size_t)N_NODES * HID];     // relu(b1 + ...)
__device__ __align__(256) float g_h2s [(size_t)N_NODES * OUT_CH];  // dinv*(out1@W2)

// ---------------- CSR build ----------------

__global__ void k_zero_cnt() {
    int i = blockIdx.x * blockDim.x + threadIdx.x;
    if (i < N_NODES) g_cnt[i] = 0;
}

__global__ void k_cnt(const int* __restrict__ dst) {
    int e = blockIdx.x * blockDim.x + threadIdx.x;
    if (e < N_EDGES) atomicAdd(&g_cnt[dst[e]], 1);
}

__global__ void k_dinv() {
    int i = blockIdx.x * blockDim.x + threadIdx.x;
    if (i < N_NODES) g_dinv[i] = rsqrtf((float)(g_cnt[i] + 1));  // + self loop
}

__global__ void __launch_bounds__(SCAN_BLK) k_scan1() {
    __shared__ int s[2 * SCAN_BLK];
    int t = threadIdx.x;
    int gi = blockIdx.x * SCAN_BLK + t;
    int v = (gi < N_NODES) ? g_cnt[gi] : 0;
    int* a = s; int* b = s + SCAN_BLK;
    a[t] = v;
    __syncthreads();
#pragma unroll
    for (int off = 1; off < SCAN_BLK; off <<= 1) {
        b[t] = a[t] + ((t >= off) ? a[t - off] : 0);
        int* tmp = a; a = b; b = tmp;
        __syncthreads();
    }
    if (gi < N_NODES) g_offs[gi] = a[t] - v;   // exclusive, block-local
    if (t == SCAN_BLK - 1) g_bsum[blockIdx.x] = a[t];
}

// parallel scan of 157 block sums (one 256-thread block) — replaces 9.2us serial loop
__global__ void __launch_bounds__(256) k_scan2() {
    __shared__ int s[2 * 256];
    int t = threadIdx.x;
    int v = (t < N_SCAN_BLOCKS) ? g_bsum[t] : 0;
    int* a = s; int* b = s + 256;
    a[t] = v;
    __syncthreads();
#pragma unroll
    for (int off = 1; off < 256; off <<= 1) {
        b[t] = a[t] + ((t >= off) ? a[t - off] : 0);
        int* tmp = a; a = b; b = tmp;
        __syncthreads();
    }
    if (t < N_SCAN_BLOCKS) g_bsum[t] = a[t] - v;   // exclusive
    if (t == 0) g_offs[N_NODES] = N_EDGES;
}

__global__ void k_scan3() {
    int gi = blockIdx.x * blockDim.x + threadIdx.x;
    if (gi < N_NODES) {
        int o = g_offs[gi] + g_bsum[gi / SCAN_BLK];
        g_offs[gi] = o;
        g_cursor[gi] = o;
    }
}

__global__ void k_fill(const int* __restrict__ src, const int* __restrict__ dst) {
    int e = blockIdx.x * blockDim.x + threadIdx.x;
    if (e < N_EDGES) {
        int pos = atomicAdd(&g_cursor[dst[e]], 1);
        g_csr[pos] = src[e];
    }
}

// ---------------- GEMM1: h1s = dinv * (x @ W1) (128 -> 64) ----------------
// R3/R4-proven: 128 threads/block, tile 128 nodes x 64 ch, thread = 4 nodes x 16 ch.

__global__ void __launch_bounds__(128) k_gemm1(const float* __restrict__ x,
                                               const float* __restrict__ W1) {
    __shared__ float sW[32 * 64];
    __shared__ float sX[128 * 33];
    const int tn = threadIdx.x & 3;
    const int tm = threadIdx.x >> 2;
    const int cg = tn << 4;
    const int nodeBase = blockIdx.x * 128;

    float acc[4][16];
#pragma unroll
    for (int j = 0; j < 4; j++)
#pragma unroll
        for (int c = 0; c < 16; c++) acc[j][c] = 0.0f;

    for (int kt = 0; kt < IN_CH; kt += 32) {
#pragma unroll
        for (int i = threadIdx.x; i < 512; i += 128)
            ((float4*)sW)[i] =
                ((const float4*)W1)[(size_t)(kt + (i >> 4)) * 16 + (i & 15)];
#pragma unroll
        for (int i = threadIdx.x; i < 1024; i += 128) {
            int n = i >> 3, f4 = i & 7;
            float4 v = ((const float4*)x)[(size_t)(nodeBase + n) * 32 + (kt >> 2) + f4];
            float* p = sX + n * 33 + (f4 << 2);
            p[0] = v.x; p[1] = v.y; p[2] = v.z; p[3] = v.w;
        }
        __syncthreads();
#pragma unroll 2
        for (int k = 0; k < 32; ++k) {
            const float4* w4 = (const float4*)(sW + k * 64 + cg);
            float4 w0 = w4[0], w1 = w4[1], w2 = w4[2], w3 = w4[3];
            float xv[4];
#pragma unroll
            for (int j = 0; j < 4; j++) xv[j] = sX[(tm * 4 + j) * 33 + k];
#pragma unroll
            for (int j = 0; j < 4; j++) {
                acc[j][0]  += xv[j] * w0.x;  acc[j][1]  += xv[j] * w0.y;
                acc[j][2]  += xv[j] * w0.z;  acc[j][3]  += xv[j] * w0.w;
                acc[j][4]  += xv[j] * w1.x;  acc[j][5]  += xv[j] * w1.y;
                acc[j][6]  += xv[j] * w1.z;  acc[j][7]  += xv[j] * w1.w;
                acc[j][8]  += xv[j] * w2.x;  acc[j][9]  += xv[j] * w2.y;
                acc[j][10] += xv[j] * w2.z;  acc[j][11] += xv[j] * w2.w;
                acc[j][12] += xv[j] * w3.x;  acc[j][13] += xv[j] * w3.y;
                acc[j][14] += xv[j] * w3.z;  acc[j][15] += xv[j] * w3.w;
            }
        }
        __syncthreads();
    }
#pragma unroll
    for (int j = 0; j < 4; j++) {
        int node = nodeBase + tm * 4 + j;
        float dj = g_dinv[node];
        float4* out = (float4*)(g_h1s + (size_t)node * HID + cg);
#pragma unroll
        for (int q = 0; q < 4; q++)
            out[q] = make_float4(dj * acc[j][4 * q], dj * acc[j][4 * q + 1],
                                 dj * acc[j][4 * q + 2], dj * acc[j][4 * q + 3]);
    }
}

// ---------------- agg1 (warp/node, lane = 2 ch, MLP-1 — R4 proven) ----------------

__global__ void __launch_bounds__(256) k_agg1(const float* __restrict__ b1) {
    int node = blockIdx.x * 8 + (threadIdx.x >> 5);
    if (node >= N_NODES) return;
    int lane = threadIdx.x & 31;
    const float2* h = (const float2*)g_h1s;
    int beg = g_offs[node], end = g_offs[node + 1];
    float2 acc = h[(size_t)node * 32 + lane];   // self
    for (int c = beg; c < end; c += 32) {
        int idx = (c + lane < end) ? g_csr[c + lane] : 0;
        int m = min(32, end - c);
        for (int t = 0; t < m; ++t) {
            int j = __shfl_sync(0xffffffffu, idx, t);
            float2 v = h[(size_t)j * 32 + lane];
            acc.x += v.x; acc.y += v.y;
        }
    }
    float di = g_dinv[node];
    float2 bv = ((const float2*)b1)[lane];
    ((float2*)g_out1)[(size_t)node * 32 + lane] =
        make_float2(fmaxf(bv.x + di * acc.x, 0.0f),
                    fmaxf(bv.y + di * acc.y, 0.0f));
}

// ---------------- GEMM2: h2s = dinv * (out1 @ W2) (64 -> 32) ----------------

__global__ void __launch_bounds__(128) k_gemm2(const float* __restrict__ W2) {
    __shared__ float sW[64 * 32];
    __shared__ float sX[128 * 65];
    const int tn = threadIdx.x & 3;
    const int tm = threadIdx.x >> 2;
    const int cg = tn << 3;
    const int nodeBase = blockIdx.x * 128;

#pragma unroll
    for (int i = threadIdx.x; i < 512; i += 128)
        ((float4*)sW)[i] = ((const float4*)W2)[i];
#pragma unroll
    for (int i = threadIdx.x; i < 2048; i += 128) {
        int n = i >> 4, f4 = i & 15;
        float4 v = ((const float4*)g_out1)[(size_t)(nodeBase + n) * 16 + f4];
        float* p = sX + n * 65 + (f4 << 2);
        p[0] = v.x; p[1] = v.y; p[2] = v.z; p[3] = v.w;
    }
    __syncthreads();

    float acc[4][8];
#pragma unroll
    for (int j = 0; j < 4; j++)
#pragma unroll
        for (int c = 0; c < 8; c++) acc[j][c] = 0.0f;

#pragma unroll 4
    for (int k = 0; k < HID; ++k) {
        const float4* w4 = (const float4*)(sW + k * 32 + cg);
        float4 w0 = w4[0], w1 = w4[1];
        float xv[4];
#pragma unroll
        for (int j = 0; j < 4; j++) xv[j] = sX[(tm * 4 + j) * 65 + k];
#pragma unroll
        for (int j = 0; j < 4; j++) {
            acc[j][0] += xv[j] * w0.x; acc[j][1] += xv[j] * w0.y;
            acc[j][2] += xv[j] * w0.z; acc[j][3] += xv[j] * w0.w;
            acc[j][4] += xv[j] * w1.x; acc[j][5] += xv[j] * w1.y;
            acc[j][6] += xv[j] * w1.z; acc[j][7] += xv[j] * w1.w;
        }
    }
#pragma unroll
    for (int j = 0; j < 4; j++) {
        int node = nodeBase + tm * 4 + j;
        float dj = g_dinv[node];
        float4* out = (float4*)(g_h2s + (size_t)node * OUT_CH + cg);
        out[0] = make_float4(dj * acc[j][0], dj * acc[j][1],
                             dj * acc[j][2], dj * acc[j][3]);
        out[1] = make_float4(dj * acc[j][4], dj * acc[j][5],
                             dj * acc[j][6], dj * acc[j][7]);
    }
}

// ---------------- agg2 (warp/node, lane = 1 ch, MLP-1 — R4 proven) ----------------

__global__ void __launch_bounds__(256) k_agg2(const float* __restrict__ b2,
                                              float* __restrict__ out) {
    int node = blockIdx.x * 8 + (threadIdx.x >> 5);
    if (node >= N_NODES) return;
    int lane = threadIdx.x & 31;
    int beg = g_offs[node], end = g_offs[node + 1];
    float acc = g_h2s[(size_t)node * 32 + lane];   // self
    for (int c = beg; c < end; c += 32) {
        int idx = (c + lane < end) ? g_csr[c + lane] : 0;
        int m = min(32, end - c);
        for (int t = 0; t < m; ++t) {
            int j = __shfl_sync(0xffffffffu, idx, t);
            acc += g_h2s[(size_t)j * 32 + lane];
        }
    }
    float di = g_dinv[node];
    out[(size_t)node * 32 + lane] = b2[lane] + di * acc;
}

// ---------------- launch (single stream, R4-proven order) ----------------

extern "C" void kernel_launch(void* const* d_in, const int* in_sizes, int n_in,
                              void* d_out, int out_size) {
    const float* x   = (const float*)d_in[0];
    const int*   ei  = (const int*)d_in[1];
    const float* W1  = (const float*)d_in[2];
    const float* b1  = (const float*)d_in[3];
    const float* W2  = (const float*)d_in[4];
    const float* b2  = (const float*)d_in[5];
    float*       out = (float*)d_out;

    const int* src = ei;
    const int* dst = ei + N_EDGES;

    k_zero_cnt<<<(N_NODES + 255) / 256, 256>>>();
    k_cnt     <<<(N_EDGES + 255) / 256, 256>>>(dst);
    k_dinv    <<<(N_NODES + 255) / 256, 256>>>();
    k_scan1   <<<N_SCAN_BLOCKS, SCAN_BLK>>>();
    k_scan2   <<<1, 256>>>();
    k_scan3   <<<(N_NODES + 255) / 256, 256>>>();
    k_fill    <<<(N_EDGES + 255) / 256, 256>>>(src, dst);

    k_gemm1   <<<N_NODES / 128, 128>>>(x, W1);
    k_agg1    <<<(N_NODES + 7) / 8, 256>>>(b1);
    k_gemm2   <<<N_NODES / 128, 128>>>(W2);
    k_agg2    <<<(N_NODES + 7) / 8, 256>>>(b2, out);
}